// round 1
// baseline (speedup 1.0000x reference)
#include <cuda_runtime.h>
#include <math.h>

#define NB 16
#define NC 80
#define NLOC 17064
#define CAND_CAP 262144
#define NBUCK 16384
#define SEL_CAP 4096
#define TOPK 1000
#define MAXDET 100
#define NEGINF (__int_as_float((int)0xff800000))

// ---------------- static device scratch (no allocations) ----------------
__device__ unsigned long long g_cand[(size_t)NB * CAND_CAP];  // (score_bits<<32)|idx
__device__ int g_hist[NB * NBUCK];
__device__ int g_candCount[NB];
__device__ int g_selCount[NB];
__device__ int g_thr[NB];
__device__ unsigned long long g_sel[NB * SEL_CAP];            // (score_bits<<32)|(~idx)
__device__ float g_box[NB * TOPK * 4];
__device__ float g_sc[NB * TOPK];
__device__ float g_cls[NB * TOPK];

// ---------------- pass 0: zero scratch ----------------
__global__ void zero_kernel() {
    int i = blockIdx.x * blockDim.x + threadIdx.x;
    if (i < NB * NBUCK) g_hist[i] = 0;
    if (i < NB) { g_candCount[i] = 0; g_selCount[i] = 0; }
}

// ---------------- pass 1: scores + candidate list + histogram ----------------
__global__ __launch_bounds__(256) void pass1_kernel(
    const float* __restrict__ logits, const float* __restrict__ ctr,
    int CHW, int HW, int locOff)
{
    int b = blockIdx.y;
    const float* lg = logits + (size_t)b * CHW;
    const float* ct = ctr + (size_t)b * HW;
    int lane = threadIdx.x & 31;
    int stride = gridDim.x * blockDim.x;
    for (int e = blockIdx.x * blockDim.x + threadIdx.x; (e - lane) < CHW; e += stride) {
        bool in = e < CHW;
        float cls = 0.0f;
        if (in) {
            float x = lg[e];
            cls = 1.0f / (1.0f + expf(-x));
        }
        bool pos = in && (cls > 0.05f);
        unsigned m = __ballot_sync(0xFFFFFFFFu, pos);
        if (m == 0) continue;
        unsigned bits = 0, idx = 0;
        if (pos) {
            int hw = e % HW;
            int c  = e / HW;
            float cen  = 1.0f / (1.0f + expf(-ct[hw]));
            float comb = cls * cen;                  // > 0 strictly
            bits = __float_as_uint(comb);
            atomicAdd(&g_hist[b * NBUCK + (bits >> 17)], 1);
            idx = (unsigned)((locOff + hw) * NC + c);
        }
        int n = __popc(m);
        int leader = __ffs(m) - 1;
        int base = 0;
        if (lane == leader) base = atomicAdd(&g_candCount[b], n);
        base = __shfl_sync(0xFFFFFFFFu, base, leader);
        if (pos) {
            int p = base + __popc(m & ((1u << lane) - 1u));
            if (p < CAND_CAP)
                g_cand[(size_t)b * CAND_CAP + p] =
                    ((unsigned long long)bits << 32) | (unsigned long long)idx;
        }
    }
}

// ---------------- pass 2: per-batch histogram threshold ----------------
__global__ void pass2_kernel() {
    int b = blockIdx.x;
    __shared__ int csum[256];
    int t = threadIdx.x;
    int s = 0;
    for (int r = t * 64; r < t * 64 + 64; r++)
        s += g_hist[b * NBUCK + (NBUCK - 1 - r)];
    csum[t] = s;
    __syncthreads();
    if (t == 0) {
        int cum = 0, thr = 0;
        bool found = false;
        for (int j = 0; j < 256 && !found; j++) {
            if (cum + csum[j] >= TOPK) {
                for (int r = j * 64; r < j * 64 + 64; r++) {
                    cum += g_hist[b * NBUCK + (NBUCK - 1 - r)];
                    if (cum >= TOPK) { thr = NBUCK - 1 - r; found = true; break; }
                }
            } else {
                cum += csum[j];
            }
        }
        g_thr[b] = thr;   // 0 => take everything (fewer than TOPK positives)
    }
}

// ---------------- pass 3: gather candidates above threshold ----------------
__global__ __launch_bounds__(256) void pass3_kernel() {
    int b = blockIdx.y;
    int count = min(g_candCount[b], CAND_CAP);
    unsigned thr = (unsigned)g_thr[b];
    int lane = threadIdx.x & 31;
    int stride = gridDim.x * blockDim.x;
    for (int e = blockIdx.x * blockDim.x + threadIdx.x; (e - lane) < count; e += stride) {
        bool in = e < count;
        unsigned long long k = 0ULL;
        bool sel = false;
        if (in) {
            k = g_cand[(size_t)b * CAND_CAP + e];
            sel = (((unsigned)(k >> 32)) >> 17) >= thr;
        }
        unsigned m = __ballot_sync(0xFFFFFFFFu, sel);
        if (m == 0) continue;
        int n = __popc(m);
        int leader = __ffs(m) - 1;
        int base = 0;
        if (lane == leader) base = atomicAdd(&g_selCount[b], n);
        base = __shfl_sync(0xFFFFFFFFu, base, leader);
        if (sel) {
            int p = base + __popc(m & ((1u << lane) - 1u));
            if (p < SEL_CAP)
                g_sel[b * SEL_CAP + p] =
                    (k & 0xFFFFFFFF00000000ULL) |
                    (unsigned long long)(0xFFFFFFFFu - (unsigned)(k & 0xFFFFFFFFu));
        }
    }
}

// ---------------- pass 4: per-batch sort (desc, idx-asc ties) + decode ----------------
__global__ __launch_bounds__(1024) void pass4_kernel(
    const float* __restrict__ bb0, const float* __restrict__ bb1,
    const float* __restrict__ bb2, const float* __restrict__ bb3,
    const float* __restrict__ bb4, const float* __restrict__ iminfo)
{
    int b = blockIdx.x;
    __shared__ unsigned long long key[SEL_CAP];
    int cnt = min(g_selCount[b], SEL_CAP);
    for (int i = threadIdx.x; i < SEL_CAP; i += blockDim.x)
        key[i] = (i < cnt) ? g_sel[b * SEL_CAP + i] : 0ULL;
    __syncthreads();
    // bitonic sort, descending
    for (int k = 2; k <= SEL_CAP; k <<= 1) {
        for (int j = k >> 1; j > 0; j >>= 1) {
            for (int i = threadIdx.x; i < SEL_CAP; i += blockDim.x) {
                int ixj = i ^ j;
                if (ixj > i) {
                    bool desc = (i & k) == 0;
                    unsigned long long a = key[i], c = key[ixj];
                    bool sw = desc ? (a < c) : (a > c);
                    if (sw) { key[i] = c; key[ixj] = a; }
                }
            }
            __syncthreads();
        }
    }
    if (threadIdx.x < TOPK) {
        int r = threadIdx.x;
        unsigned long long kk = key[r];
        unsigned bits = (unsigned)(kk >> 32);
        float x1 = 0.f, y1 = 0.f, x2 = 0.f, y2 = 0.f, sc = 0.f, cf = 0.f;
        if (bits != 0u) {
            unsigned idx = 0xFFFFFFFFu - (unsigned)(kk & 0xFFFFFFFFu);
            int loc = (int)(idx / NC);
            int c   = (int)(idx % NC);
            const int offs[5]    = {0, 12800, 16000, 16800, 17008};
            const int Ws[5]      = {128, 64, 32, 16, 8};
            const int HWs[5]     = {12800, 3200, 800, 208, 56};
            const int strides[5] = {8, 16, 32, 64, 128};
            const float* bbs[5]  = {bb0, bb1, bb2, bb3, bb4};
            int lvl = 4;
            if      (loc < 12800) lvl = 0;
            else if (loc < 16000) lvl = 1;
            else if (loc < 16800) lvl = 2;
            else if (loc < 17008) lvl = 3;
            int local = loc - offs[lvl];
            int W = Ws[lvl], HW = HWs[lvl], st = strides[lvl];
            int hh = local / W;
            int ww = local - hh * W;
            float cx = (float)(ww * st + (st >> 1));
            float cy = (float)(hh * st + (st >> 1));
            const float* bp = bbs[lvl] + (size_t)b * 4 * HW + local;
            float r0 = bp[0], r1 = bp[HW], r2 = bp[2 * HW], r3 = bp[3 * HW];
            float ih = iminfo[b * 2 + 0];
            float iw = iminfo[b * 2 + 1];
            x1 = fminf(fmaxf(cx - r0, 0.0f), iw - 1.0f);
            y1 = fminf(fmaxf(cy - r1, 0.0f), ih - 1.0f);
            x2 = fminf(fmaxf(cx + r2, 0.0f), iw - 1.0f);
            y2 = fminf(fmaxf(cy + r3, 0.0f), ih - 1.0f);
            float val = __uint_as_float(bits);
            sc = sqrtf(val + 1e-12f);
            cf = (float)c;
        }
        float* bx = &g_box[(b * TOPK + r) * 4];
        bx[0] = x1; bx[1] = y1; bx[2] = x2; bx[3] = y2;
        g_sc[b * TOPK + r]  = sc;
        g_cls[b * TOPK + r] = cf;
    }
}

// ---------------- pass 5: per-batch sequential NMS (matches reference exactly) ----------------
__global__ __launch_bounds__(1024) void pass5_kernel(float* __restrict__ out) {
    int b = blockIdx.x;
    int t = threadIdx.x;
    __shared__ float sx1[TOPK], sy1[TOPK], sx2[TOPK], sy2[TOPK];
    __shared__ float scl[TOPK], ssc[TOPK], sar[TOPK];
    __shared__ float wS[32];
    __shared__ int   wI[32];
    __shared__ float bestS;
    __shared__ int   bestI;

    if (t < TOPK) {
        const float* bx = &g_box[(b * TOPK + t) * 4];
        float x1 = bx[0], y1 = bx[1], x2 = bx[2], y2 = bx[3];
        float cf = g_cls[b * TOPK + t];
        float off = cf * 10000.0f;
        // area computed on OFFSET coords, same fp32 rounding as reference
        float ox1 = x1 + off, oy1 = y1 + off, ox2 = x2 + off, oy2 = y2 + off;
        sx1[t] = x1; sy1[t] = y1; sx2[t] = x2; sy2[t] = y2;
        scl[t] = cf;
        sar[t] = fmaxf(ox2 - ox1, 0.0f) * fmaxf(oy2 - oy1, 0.0f);
        ssc[t] = g_sc[b * TOPK + t];
    }
    __syncthreads();

    for (int it = 0; it < MAXDET; it++) {
        float s = (t < TOPK) ? ssc[t] : NEGINF;
        int i = t;
        #pragma unroll
        for (int d = 16; d > 0; d >>= 1) {
            float s2 = __shfl_down_sync(0xFFFFFFFFu, s, d);
            int   i2 = __shfl_down_sync(0xFFFFFFFFu, i, d);
            if (s2 > s || (s2 == s && i2 < i)) { s = s2; i = i2; }
        }
        if ((t & 31) == 0) { wS[t >> 5] = s; wI[t >> 5] = i; }
        __syncthreads();
        if (t < 32) {
            s = wS[t]; i = wI[t];
            #pragma unroll
            for (int d = 16; d > 0; d >>= 1) {
                float s2 = __shfl_down_sync(0xFFFFFFFFu, s, d);
                int   i2 = __shfl_down_sync(0xFFFFFFFFu, i, d);
                if (s2 > s || (s2 == s && i2 < i)) { s = s2; i = i2; }
            }
            if (t == 0) { bestS = s; bestI = i; }
        }
        __syncthreads();
        int bi = bestI;
        float bs = bestS;
        if (t == 0) {
            float* o = out + (size_t)(b * MAXDET + it) * 6;
            bool valid = bs > 0.0f;
            o[0] = valid ? sx1[bi] : 0.0f;
            o[1] = valid ? sy1[bi] : 0.0f;
            o[2] = valid ? sx2[bi] : 0.0f;
            o[3] = valid ? sy2[bi] : 0.0f;
            o[4] = valid ? bs      : 0.0f;
            o[5] = valid ? scl[bi] : 0.0f;
        }
        if (t < TOPK) {
            float offi = scl[bi] * 10000.0f;
            float offt = scl[t]  * 10000.0f;
            float bx1 = sx1[bi] + offi, by1 = sy1[bi] + offi;
            float bx2 = sx2[bi] + offi, by2 = sy2[bi] + offi;
            float tx1 = sx1[t] + offt, ty1 = sy1[t] + offt;
            float tx2 = sx2[t] + offt, ty2 = sy2[t] + offt;
            float xx1 = fmaxf(bx1, tx1), yy1 = fmaxf(by1, ty1);
            float xx2 = fminf(bx2, tx2), yy2 = fminf(by2, ty2);
            float inter = fmaxf(xx2 - xx1, 0.0f) * fmaxf(yy2 - yy1, 0.0f);
            float iou = inter / (sar[bi] + sar[t] - inter + 1e-9f);
            if (iou >= 0.6f || t == bi) ssc[t] = NEGINF;
        }
        __syncthreads();
    }
}

// ---------------- launch ----------------
extern "C" void kernel_launch(void* const* d_in, const int* in_sizes, int n_in,
                              void* d_out, int out_size) {
    (void)in_sizes; (void)n_in; (void)out_size;
    const float* lg[5]; const float* bb[5]; const float* ct[5];
    for (int l = 0; l < 5; l++) {
        lg[l] = (const float*)d_in[3 * l + 0];
        bb[l] = (const float*)d_in[3 * l + 1];
        ct[l] = (const float*)d_in[3 * l + 2];
    }
    const float* iminfo = (const float*)d_in[15];
    float* out = (float*)d_out;

    zero_kernel<<<(NB * NBUCK + 255) / 256, 256>>>();

    const int HWs[5]  = {12800, 3200, 800, 208, 56};
    const int offs[5] = {0, 12800, 16000, 16800, 17008};
    for (int l = 0; l < 5; l++) {
        int CHW = NC * HWs[l];
        int gx = (CHW + 256 * 16 - 1) / (256 * 16);
        pass1_kernel<<<dim3(gx, NB), 256>>>(lg[l], ct[l], CHW, HWs[l], offs[l]);
    }
    pass2_kernel<<<NB, 256>>>();
    pass3_kernel<<<dim3(64, NB), 256>>>();
    pass4_kernel<<<NB, 1024>>>(bb[0], bb[1], bb[2], bb[3], bb[4], iminfo);
    pass5_kernel<<<NB, 1024>>>(out);
}

// round 2
// speedup vs baseline: 1.4004x; 1.4004x over previous
#include <cuda_runtime.h>
#include <math.h>

#define NB 16
#define NC 80
#define CAND_CAP 262144
#define NBUCK 16384
#define SEL_CAP 4096
#define TOPK 1000
#define MAXDET 100

// ---------------- static device scratch (no allocations) ----------------
__device__ unsigned long long g_cand[(size_t)NB * CAND_CAP];  // (score_bits<<32)|idx
__device__ int g_hist[NB * NBUCK];
__device__ int g_candCount[NB];
__device__ int g_selCount[NB];
__device__ int g_thr[NB];
__device__ unsigned long long g_sel[NB * SEL_CAP];            // (score_bits<<32)|(~idx)

// ---------------- pass 0: zero scratch ----------------
__global__ void zero_kernel() {
    int i = blockIdx.x * blockDim.x + threadIdx.x;
    if (i < NB * NBUCK) g_hist[i] = 0;
    if (i < NB) { g_candCount[i] = 0; g_selCount[i] = 0; }
}

// ---------------- pass 1: fused all-level scoring ----------------
// Each block handles a 4096-element chunk of one (level, batch).
// Positives staged in shared memory; ONE global atomic per block.

template<int HW, int LOCOFF>
__device__ __forceinline__ void score_level(
    const float* __restrict__ lg, const float* __restrict__ ct,
    int b, int chunk, unsigned long long* stage, int* s_cnt)
{
    constexpr int CHW = NC * HW;
    const float* lp = lg + (size_t)b * CHW;
    const float* cp = ct + (size_t)b * HW;
    int base = chunk * 4096;
    #pragma unroll
    for (int k = 0; k < 4; k++) {
        int e = base + (threadIdx.x + k * 256) * 4;
        if (e >= CHW) continue;
        float4 v = *reinterpret_cast<const float4*>(lp + e);
        int c  = e / HW;            // constant division -> mul/shift
        int hw = e - c * HW;
        float xs[4] = {v.x, v.y, v.z, v.w};
        #pragma unroll
        for (int i = 0; i < 4; i++) {
            float x = xs[i];
            if (x > -2.9445f) {     // prefilter: sigmoid(-2.9445) < 0.05 by wide margin
                float cls = 1.0f / (1.0f + expf(-x));
                if (cls > 0.05f) {
                    float cen  = 1.0f / (1.0f + expf(-cp[hw + i]));
                    float comb = cls * cen;              // strictly > 0
                    unsigned bits = __float_as_uint(comb);
                    atomicAdd(&g_hist[b * NBUCK + (bits >> 17)], 1);
                    unsigned idx = (unsigned)((LOCOFF + hw + i) * NC + c);
                    int p = atomicAdd(s_cnt, 1);
                    stage[p] = ((unsigned long long)bits << 32) | (unsigned long long)idx;
                }
            }
        }
    }
}

__global__ __launch_bounds__(256) void score_kernel(
    const float* __restrict__ lg0, const float* __restrict__ ct0,
    const float* __restrict__ lg1, const float* __restrict__ ct1,
    const float* __restrict__ lg2, const float* __restrict__ ct2,
    const float* __restrict__ lg3, const float* __restrict__ ct3,
    const float* __restrict__ lg4, const float* __restrict__ ct4)
{
    __shared__ unsigned long long stage[4096];
    __shared__ int s_cnt;
    __shared__ int s_base;
    if (threadIdx.x == 0) s_cnt = 0;
    __syncthreads();

    int bx = blockIdx.x;
    int b  = blockIdx.y;
    // chunk counts per level: 250, 63, 16, 5, 2  (cum 250,313,329,334,336)
    if      (bx < 250) score_level<12800,     0>(lg0, ct0, b, bx,       stage, &s_cnt);
    else if (bx < 313) score_level< 3200, 12800>(lg1, ct1, b, bx - 250, stage, &s_cnt);
    else if (bx < 329) score_level<  800, 16000>(lg2, ct2, b, bx - 313, stage, &s_cnt);
    else if (bx < 334) score_level<  208, 16800>(lg3, ct3, b, bx - 329, stage, &s_cnt);
    else               score_level<   56, 17008>(lg4, ct4, b, bx - 334, stage, &s_cnt);
    __syncthreads();

    if (threadIdx.x == 0)
        s_base = atomicAdd(&g_candCount[b], s_cnt);
    __syncthreads();

    int n = s_cnt, gb = s_base;
    for (int i = threadIdx.x; i < n; i += 256) {
        int p = gb + i;
        if (p < CAND_CAP)
            g_cand[(size_t)b * CAND_CAP + p] = stage[i];
    }
}

// ---------------- pass 2: per-batch histogram threshold ----------------
__global__ void pass2_kernel() {
    int b = blockIdx.x;
    __shared__ int csum[256];
    int t = threadIdx.x;
    int s = 0;
    for (int r = t * 64; r < t * 64 + 64; r++)
        s += g_hist[b * NBUCK + (NBUCK - 1 - r)];
    csum[t] = s;
    __syncthreads();
    if (t == 0) {
        int cum = 0, thr = 0;
        bool found = false;
        for (int j = 0; j < 256 && !found; j++) {
            if (cum + csum[j] >= TOPK) {
                for (int r = j * 64; r < j * 64 + 64; r++) {
                    cum += g_hist[b * NBUCK + (NBUCK - 1 - r)];
                    if (cum >= TOPK) { thr = NBUCK - 1 - r; found = true; break; }
                }
            } else {
                cum += csum[j];
            }
        }
        g_thr[b] = thr;   // 0 => take everything (fewer than TOPK positives)
    }
}

// ---------------- pass 3: gather candidates above threshold ----------------
__global__ __launch_bounds__(256) void pass3_kernel() {
    int b = blockIdx.y;
    int count = min(g_candCount[b], CAND_CAP);
    unsigned thr = (unsigned)g_thr[b];
    int lane = threadIdx.x & 31;
    int stride = gridDim.x * blockDim.x;
    for (int e = blockIdx.x * blockDim.x + threadIdx.x; (e - lane) < count; e += stride) {
        bool in = e < count;
        unsigned long long k = 0ULL;
        bool sel = false;
        if (in) {
            k = g_cand[(size_t)b * CAND_CAP + e];
            sel = (((unsigned)(k >> 32)) >> 17) >= thr;
        }
        unsigned m = __ballot_sync(0xFFFFFFFFu, sel);
        if (m == 0) continue;
        int n = __popc(m);
        int leader = __ffs(m) - 1;
        int base = 0;
        if (lane == leader) base = atomicAdd(&g_selCount[b], n);
        base = __shfl_sync(0xFFFFFFFFu, base, leader);
        if (sel) {
            int p = base + __popc(m & ((1u << lane) - 1u));
            if (p < SEL_CAP)
                g_sel[b * SEL_CAP + p] =
                    (k & 0xFFFFFFFF00000000ULL) |
                    (unsigned long long)(0xFFFFFFFFu - (unsigned)(k & 0xFFFFFFFFu));
        }
    }
}

// ---------------- pass 4+5 fused: sort, decode, sorted-greedy NMS ----------------
__global__ __launch_bounds__(1024) void sortnms_kernel(
    const float* __restrict__ bb0, const float* __restrict__ bb1,
    const float* __restrict__ bb2, const float* __restrict__ bb3,
    const float* __restrict__ bb4, const float* __restrict__ iminfo,
    float* __restrict__ out)
{
    int b = blockIdx.x;
    int t = threadIdx.x;

    __shared__ union {
        unsigned long long key[SEL_CAP];                       // 32 KB
        struct {
            float x1[1024], y1[1024], x2[1024], y2[1024];      // plain clipped coords
            float ar[1024], sc[1024], cf[1024];                // area(on offset), score, class
        } d;                                                    // 28 KB (aliases key)
    } u;
    __shared__ unsigned s_alive[32];
    __shared__ int s_best;

    int cnt = min(g_selCount[b], SEL_CAP);
    for (int i = t; i < SEL_CAP; i += blockDim.x)
        u.key[i] = (i < cnt) ? g_sel[b * SEL_CAP + i] : 0ULL;
    __syncthreads();

    // bitonic sort descending: key = (score_bits<<32)|(~idx) -> desc score, asc idx ties
    for (int k = 2; k <= SEL_CAP; k <<= 1) {
        for (int j = k >> 1; j > 0; j >>= 1) {
            for (int i = t; i < SEL_CAP; i += blockDim.x) {
                int ixj = i ^ j;
                if (ixj > i) {
                    bool desc = (i & k) == 0;
                    unsigned long long a = u.key[i], c = u.key[ixj];
                    if (desc ? (a < c) : (a > c)) { u.key[i] = c; u.key[ixj] = a; }
                }
            }
            __syncthreads();
        }
    }

    // Decode top-1000 into registers, then overwrite the union with box arrays.
    unsigned long long myKey = (t < TOPK) ? u.key[t] : 0ULL;
    __syncthreads();

    if (t < TOPK) {
        unsigned bits = (unsigned)(myKey >> 32);
        float x1 = 0.f, y1 = 0.f, x2 = 0.f, y2 = 0.f, sc = 0.f, cf = 0.f;
        if (bits != 0u) {
            unsigned idx = 0xFFFFFFFFu - (unsigned)(myKey & 0xFFFFFFFFu);
            int loc = (int)(idx / NC);
            int c   = (int)(idx % NC);
            const int offs[5]    = {0, 12800, 16000, 16800, 17008};
            const int Ws[5]      = {128, 64, 32, 16, 8};
            const int HWs[5]     = {12800, 3200, 800, 208, 56};
            const int strides[5] = {8, 16, 32, 64, 128};
            const float* bbs[5]  = {bb0, bb1, bb2, bb3, bb4};
            int lvl = 4;
            if      (loc < 12800) lvl = 0;
            else if (loc < 16000) lvl = 1;
            else if (loc < 16800) lvl = 2;
            else if (loc < 17008) lvl = 3;
            int local = loc - offs[lvl];
            int W = Ws[lvl], HW = HWs[lvl], st = strides[lvl];
            int hh = local / W;
            int ww = local - hh * W;
            float cx = (float)(ww * st + (st >> 1));
            float cy = (float)(hh * st + (st >> 1));
            const float* bp = bbs[lvl] + (size_t)b * 4 * HW + local;
            float r0 = bp[0], r1 = bp[HW], r2 = bp[2 * HW], r3 = bp[3 * HW];
            float ih = iminfo[b * 2 + 0];
            float iw = iminfo[b * 2 + 1];
            x1 = fminf(fmaxf(cx - r0, 0.0f), iw - 1.0f);
            y1 = fminf(fmaxf(cy - r1, 0.0f), ih - 1.0f);
            x2 = fminf(fmaxf(cx + r2, 0.0f), iw - 1.0f);
            y2 = fminf(fmaxf(cy + r3, 0.0f), ih - 1.0f);
            sc = sqrtf(__uint_as_float(bits) + 1e-12f);
            cf = (float)c;
        }
        // area on class-offset coords (same fp32 rounding as reference)
        float off = cf * 10000.0f;
        float ox1 = x1 + off, oy1 = y1 + off, ox2 = x2 + off, oy2 = y2 + off;
        u.d.x1[t] = x1; u.d.y1[t] = y1; u.d.x2[t] = x2; u.d.y2[t] = y2;
        u.d.ar[t] = fmaxf(ox2 - ox1, 0.0f) * fmaxf(oy2 - oy1, 0.0f);
        u.d.sc[t] = sc; u.d.cf[t] = cf;
    }
    if (t < 32) s_alive[t] = (t < 31) ? 0xFFFFFFFFu : 0x000000FFu;  // 1000 bits
    __syncthreads();

    // Sorted-greedy NMS: first-alive == argmax of remaining (list is sorted desc,
    // ties ordered by ascending original index = top_k order).
    for (int it = 0; it < MAXDET; it++) {
        if (t < 32) {
            unsigned w = s_alive[t];
            int pos = w ? (t * 32 + __ffs(w) - 1) : 0x7FFFFFFF;
            #pragma unroll
            for (int d = 16; d > 0; d >>= 1)
                pos = min(pos, __shfl_down_sync(0xFFFFFFFFu, pos, d));
            if (t == 0) s_best = pos;
        }
        __syncthreads();
        int bi = s_best;
        bool haveBest = (bi < TOPK);
        if (t == 0) {
            float bs = haveBest ? u.d.sc[bi] : 0.0f;
            bool valid = bs > 0.0f;
            float* o = out + (size_t)(b * MAXDET + it) * 6;
            o[0] = valid ? u.d.x1[bi] : 0.0f;
            o[1] = valid ? u.d.y1[bi] : 0.0f;
            o[2] = valid ? u.d.x2[bi] : 0.0f;
            o[3] = valid ? u.d.y2[bi] : 0.0f;
            o[4] = valid ? bs         : 0.0f;
            o[5] = valid ? u.d.cf[bi] : 0.0f;
        }
        bool sup = false;
        if (haveBest && t < TOPK) {
            if (t == bi) {
                sup = true;
            } else {
                float offi = u.d.cf[bi] * 10000.0f;
                float offt = u.d.cf[t]  * 10000.0f;
                float bx1 = u.d.x1[bi] + offi, by1 = u.d.y1[bi] + offi;
                float bx2 = u.d.x2[bi] + offi, by2 = u.d.y2[bi] + offi;
                float tx1 = u.d.x1[t] + offt,  ty1 = u.d.y1[t] + offt;
                float tx2 = u.d.x2[t] + offt,  ty2 = u.d.y2[t] + offt;
                float xx1 = fmaxf(bx1, tx1), yy1 = fmaxf(by1, ty1);
                float xx2 = fminf(bx2, tx2), yy2 = fminf(by2, ty2);
                float inter = fmaxf(xx2 - xx1, 0.0f) * fmaxf(yy2 - yy1, 0.0f);
                float iou = inter / (u.d.ar[bi] + u.d.ar[t] - inter + 1e-9f);
                sup = (iou >= 0.6f);
            }
        }
        unsigned m = __ballot_sync(0xFFFFFFFFu, sup);
        if ((t & 31) == 0 && m) s_alive[t >> 5] &= ~m;
        __syncthreads();
    }
}

// ---------------- launch ----------------
extern "C" void kernel_launch(void* const* d_in, const int* in_sizes, int n_in,
                              void* d_out, int out_size) {
    (void)in_sizes; (void)n_in; (void)out_size;
    const float* lg[5]; const float* bb[5]; const float* ct[5];
    for (int l = 0; l < 5; l++) {
        lg[l] = (const float*)d_in[3 * l + 0];
        bb[l] = (const float*)d_in[3 * l + 1];
        ct[l] = (const float*)d_in[3 * l + 2];
    }
    const float* iminfo = (const float*)d_in[15];
    float* out = (float*)d_out;

    zero_kernel<<<(NB * NBUCK + 255) / 256, 256>>>();
    score_kernel<<<dim3(336, NB), 256>>>(lg[0], ct[0], lg[1], ct[1], lg[2], ct[2],
                                         lg[3], ct[3], lg[4], ct[4]);
    pass2_kernel<<<NB, 256>>>();
    pass3_kernel<<<dim3(64, NB), 256>>>();
    sortnms_kernel<<<NB, 1024>>>(bb[0], bb[1], bb[2], bb[3], bb[4], iminfo, out);
}

// round 3
// speedup vs baseline: 2.2945x; 1.6385x over previous
#include <cuda_runtime.h>
#include <math.h>

#define NB 16
#define NC 80
#define CAND_CAP 262144
#define NBUCK 16384
#define REP 4
#define SEL_CAP 4096
#define TOPK 1000
#define MAXDET 100

// ---------------- static device scratch (no allocations) ----------------
__device__ unsigned long long g_cand[(size_t)NB * CAND_CAP];  // (score_bits<<32)|idx
__device__ int g_hist[NB * REP * NBUCK];
__device__ int g_candCount[NB];
__device__ int g_selCount[NB];
__device__ int g_thr[NB];
__device__ unsigned long long g_sel[NB * SEL_CAP];            // (score_bits<<32)|(~idx)

__global__ void dummy_kernel() {}

// ---------------- pass 0: zero scratch ----------------
__global__ void zero_kernel() {
    int i = blockIdx.x * blockDim.x + threadIdx.x;
    int4* p = reinterpret_cast<int4*>(g_hist);
    if (i < NB * REP * NBUCK / 4) p[i] = make_int4(0, 0, 0, 0);
    if (i < NB) { g_candCount[i] = 0; g_selCount[i] = 0; }
}

// ---------------- pass 1: fused all-level scoring ----------------
template<int HW, int LOCOFF>
__device__ __forceinline__ void score_level(
    const float* __restrict__ lg, const float* __restrict__ ct,
    int b, int chunk, int rep, unsigned long long* stage, int* s_cnt)
{
    constexpr int CHW = NC * HW;
    const float* lp = lg + (size_t)b * CHW;
    const float* cp = ct + (size_t)b * HW;
    int* hist = &g_hist[(b * REP + rep) * NBUCK];
    int base = chunk * 4096;
    int lane = threadIdx.x & 31;
    #pragma unroll
    for (int k = 0; k < 4; k++) {
        int e = base + (threadIdx.x + k * 256) * 4;
        bool in = e < CHW;
        float4 v = make_float4(-100.f, -100.f, -100.f, -100.f);
        if (in) v = *reinterpret_cast<const float4*>(lp + e);
        int c  = in ? e / HW : 0;
        int hw = in ? e - c * HW : 0;
        float xs[4] = {v.x, v.y, v.z, v.w};
        #pragma unroll
        for (int i = 0; i < 4; i++) {
            bool pos = false;
            unsigned bits = 0, idx = 0;
            float x = xs[i];
            if (x > -2.9445f) {          // sigmoid(-2.9445) < 0.05 with margin
                float cls = 1.0f / (1.0f + expf(-x));
                if (cls > 0.05f) {
                    float cen  = 1.0f / (1.0f + expf(-cp[hw + i]));
                    float comb = cls * cen;              // strictly > 0
                    bits = __float_as_uint(comb);
                    atomicAdd(&hist[bits >> 17], 1);
                    idx = (unsigned)((LOCOFF + hw + i) * NC + c);
                    pos = true;
                }
            }
            unsigned m = __ballot_sync(0xFFFFFFFFu, pos);
            if (m) {
                int leader = __ffs(m) - 1;
                int basep = 0;
                if (lane == leader) basep = atomicAdd(s_cnt, __popc(m));
                basep = __shfl_sync(0xFFFFFFFFu, basep, leader);
                if (pos)
                    stage[basep + __popc(m & ((1u << lane) - 1u))] =
                        ((unsigned long long)bits << 32) | (unsigned long long)idx;
            }
        }
    }
}

__global__ __launch_bounds__(256) void score_kernel(
    const float* __restrict__ lg0, const float* __restrict__ ct0,
    const float* __restrict__ lg1, const float* __restrict__ ct1,
    const float* __restrict__ lg2, const float* __restrict__ ct2,
    const float* __restrict__ lg3, const float* __restrict__ ct3,
    const float* __restrict__ lg4, const float* __restrict__ ct4)
{
    __shared__ unsigned long long stage[4096];
    __shared__ int s_cnt;
    __shared__ int s_base;
    if (threadIdx.x == 0) s_cnt = 0;
    __syncthreads();

    int bx = blockIdx.x;
    int b  = blockIdx.y;
    int rep = bx & (REP - 1);
    // chunk counts per level: 250, 63, 16, 5, 2  (cum 250,313,329,334,336)
    if      (bx < 250) score_level<12800,     0>(lg0, ct0, b, bx,       rep, stage, &s_cnt);
    else if (bx < 313) score_level< 3200, 12800>(lg1, ct1, b, bx - 250, rep, stage, &s_cnt);
    else if (bx < 329) score_level<  800, 16000>(lg2, ct2, b, bx - 313, rep, stage, &s_cnt);
    else if (bx < 334) score_level<  208, 16800>(lg3, ct3, b, bx - 329, rep, stage, &s_cnt);
    else               score_level<   56, 17008>(lg4, ct4, b, bx - 334, rep, stage, &s_cnt);
    __syncthreads();

    if (threadIdx.x == 0)
        s_base = atomicAdd(&g_candCount[b], s_cnt);
    __syncthreads();

    int n = s_cnt, gb = s_base;
    for (int i = threadIdx.x; i < n; i += 256) {
        int p = gb + i;
        if (p < CAND_CAP)
            g_cand[(size_t)b * CAND_CAP + p] = stage[i];
    }
}

// ---------------- pass 2: per-batch histogram threshold ----------------
__global__ void pass2_kernel() {
    int b = blockIdx.x;
    __shared__ int csum[256];
    __shared__ int sval[64];
    __shared__ int s_j, s_cumbefore;
    int t = threadIdx.x;
    const int* hb = &g_hist[b * REP * NBUCK];

    int s = 0;
    for (int r = t * 64; r < t * 64 + 64; r++) {
        int bucket = NBUCK - 1 - r;
        int v = 0;
        #pragma unroll
        for (int rp = 0; rp < REP; rp++) v += hb[rp * NBUCK + bucket];
        s += v;
    }
    csum[t] = s;
    __syncthreads();
    if (t == 0) {
        int cum = 0, j = 255;
        for (int q = 0; q < 256; q++) {
            if (cum + csum[q] >= TOPK) { j = q; break; }
            cum += csum[q];
        }
        s_j = j; s_cumbefore = cum;
    }
    __syncthreads();
    int j = s_j;
    if (t < 64) {
        int bucket = NBUCK - 1 - (j * 64 + t);
        int v = 0;
        #pragma unroll
        for (int rp = 0; rp < REP; rp++) v += hb[rp * NBUCK + bucket];
        sval[t] = v;
    }
    __syncthreads();
    if (t == 0) {
        int cum = s_cumbefore, thr = 0;
        for (int q = 0; q < 64; q++) {
            cum += sval[q];
            if (cum >= TOPK) { thr = NBUCK - 1 - (j * 64 + q); break; }
        }
        g_thr[b] = thr;   // 0 => take everything (fewer than TOPK positives)
    }
}

// ---------------- pass 3: gather candidates above threshold ----------------
__global__ __launch_bounds__(256) void pass3_kernel() {
    int b = blockIdx.y;
    int count = min(g_candCount[b], CAND_CAP);
    unsigned thr = (unsigned)g_thr[b];
    int lane = threadIdx.x & 31;
    int stride = gridDim.x * blockDim.x;
    const ulonglong2* src = reinterpret_cast<const ulonglong2*>(&g_cand[(size_t)b * CAND_CAP]);
    int nPairs = (count + 1) >> 1;
    for (int e = blockIdx.x * blockDim.x + threadIdx.x; (e - lane) < nPairs; e += stride) {
        bool in = e < nPairs;
        ulonglong2 kk = make_ulonglong2(0ULL, 0ULL);
        if (in) kk = src[e];
        bool s0 = in && ((((unsigned)(kk.x >> 32)) >> 17) >= thr);
        bool s1 = in && (2 * e + 1 < count) && ((((unsigned)(kk.y >> 32)) >> 17) >= thr);
        unsigned m0 = __ballot_sync(0xFFFFFFFFu, s0);
        unsigned m1 = __ballot_sync(0xFFFFFFFFu, s1);
        int tot = __popc(m0) + __popc(m1);
        if (tot == 0) continue;
        int base = 0;
        if (lane == 0) base = atomicAdd(&g_selCount[b], tot);
        base = __shfl_sync(0xFFFFFFFFu, base, 0);
        if (s0) {
            int p = base + __popc(m0 & ((1u << lane) - 1u));
            if (p < SEL_CAP)
                g_sel[b * SEL_CAP + p] =
                    (kk.x & 0xFFFFFFFF00000000ULL) |
                    (unsigned long long)(0xFFFFFFFFu - (unsigned)(kk.x & 0xFFFFFFFFu));
        }
        if (s1) {
            int p = base + __popc(m0) + __popc(m1 & ((1u << lane) - 1u));
            if (p < SEL_CAP)
                g_sel[b * SEL_CAP + p] =
                    (kk.y & 0xFFFFFFFF00000000ULL) |
                    (unsigned long long)(0xFFFFFFFFu - (unsigned)(kk.y & 0xFFFFFFFFu));
        }
    }
}

// ---------------- pass 4+5 fused: sort, decode, sorted-greedy NMS ----------------
__global__ __launch_bounds__(1024) void sortnms_kernel(
    const float* __restrict__ bb0, const float* __restrict__ bb1,
    const float* __restrict__ bb2, const float* __restrict__ bb3,
    const float* __restrict__ bb4, const float* __restrict__ iminfo,
    float* __restrict__ out)
{
    int b = blockIdx.x;
    int t = threadIdx.x;

    __shared__ union {
        unsigned long long key[SEL_CAP];                       // 32 KB
        struct {
            float x1[1024], y1[1024], x2[1024], y2[1024];
            float ar[1024], sc[1024], cf[1024];
        } d;                                                    // 28 KB (aliases key)
    } u;
    __shared__ unsigned s_alive[32];
    __shared__ int s_best;

    int cnt = min(g_selCount[b], SEL_CAP);
    int n2 = 1024;
    while (n2 < cnt) n2 <<= 1;        // 1024, 2048 or 4096

    for (int i = t; i < n2; i += blockDim.x)
        u.key[i] = (i < cnt) ? g_sel[b * SEL_CAP + i] : 0ULL;
    __syncthreads();

    // bitonic sort descending: key = (score_bits<<32)|(~idx)
    for (int k = 2; k <= n2; k <<= 1) {
        for (int j = k >> 1; j > 0; j >>= 1) {
            for (int i = t; i < n2; i += blockDim.x) {
                int ixj = i ^ j;
                if (ixj > i) {
                    bool desc = (i & k) == 0;
                    unsigned long long a = u.key[i], c = u.key[ixj];
                    if (desc ? (a < c) : (a > c)) { u.key[i] = c; u.key[ixj] = a; }
                }
            }
            __syncthreads();
        }
    }

    unsigned long long myKey = (t < TOPK) ? u.key[t] : 0ULL;
    __syncthreads();

    if (t < TOPK) {
        unsigned bits = (unsigned)(myKey >> 32);
        float x1 = 0.f, y1 = 0.f, x2 = 0.f, y2 = 0.f, sc = 0.f, cf = 0.f;
        if (bits != 0u) {
            unsigned idx = 0xFFFFFFFFu - (unsigned)(myKey & 0xFFFFFFFFu);
            int loc = (int)(idx / NC);
            int c   = (int)(idx % NC);
            const int offs[5]    = {0, 12800, 16000, 16800, 17008};
            const int Ws[5]      = {128, 64, 32, 16, 8};
            const int HWs[5]     = {12800, 3200, 800, 208, 56};
            const int strides[5] = {8, 16, 32, 64, 128};
            const float* bbs[5]  = {bb0, bb1, bb2, bb3, bb4};
            int lvl = 4;
            if      (loc < 12800) lvl = 0;
            else if (loc < 16000) lvl = 1;
            else if (loc < 16800) lvl = 2;
            else if (loc < 17008) lvl = 3;
            int local = loc - offs[lvl];
            int W = Ws[lvl], HW = HWs[lvl], st = strides[lvl];
            int hh = local / W;
            int ww = local - hh * W;
            float cx = (float)(ww * st + (st >> 1));
            float cy = (float)(hh * st + (st >> 1));
            const float* bp = bbs[lvl] + (size_t)b * 4 * HW + local;
            float r0 = bp[0], r1 = bp[HW], r2 = bp[2 * HW], r3 = bp[3 * HW];
            float ih = iminfo[b * 2 + 0];
            float iw = iminfo[b * 2 + 1];
            x1 = fminf(fmaxf(cx - r0, 0.0f), iw - 1.0f);
            y1 = fminf(fmaxf(cy - r1, 0.0f), ih - 1.0f);
            x2 = fminf(fmaxf(cx + r2, 0.0f), iw - 1.0f);
            y2 = fminf(fmaxf(cy + r3, 0.0f), ih - 1.0f);
            sc = sqrtf(__uint_as_float(bits) + 1e-12f);
            cf = (float)c;
        }
        float off = cf * 10000.0f;
        float ox1 = x1 + off, oy1 = y1 + off, ox2 = x2 + off, oy2 = y2 + off;
        u.d.x1[t] = x1; u.d.y1[t] = y1; u.d.x2[t] = x2; u.d.y2[t] = y2;
        u.d.ar[t] = fmaxf(ox2 - ox1, 0.0f) * fmaxf(oy2 - oy1, 0.0f);
        u.d.sc[t] = sc; u.d.cf[t] = cf;
    }
    if (t < 32) s_alive[t] = (t < 31) ? 0xFFFFFFFFu : 0x000000FFu;  // 1000 bits
    __syncthreads();

    // Sorted-greedy NMS: first-alive == argmax of remaining
    for (int it = 0; it < MAXDET; it++) {
        if (t < 32) {
            unsigned w = s_alive[t];
            int pos = w ? (t * 32 + __ffs(w) - 1) : 0x7FFFFFFF;
            #pragma unroll
            for (int d = 16; d > 0; d >>= 1)
                pos = min(pos, __shfl_down_sync(0xFFFFFFFFu, pos, d));
            if (t == 0) s_best = pos;
        }
        __syncthreads();
        int bi = s_best;
        bool haveBest = (bi < TOPK);
        if (t == 0) {
            float bs = haveBest ? u.d.sc[bi] : 0.0f;
            bool valid = bs > 0.0f;
            float* o = out + (size_t)(b * MAXDET + it) * 6;
            o[0] = valid ? u.d.x1[bi] : 0.0f;
            o[1] = valid ? u.d.y1[bi] : 0.0f;
            o[2] = valid ? u.d.x2[bi] : 0.0f;
            o[3] = valid ? u.d.y2[bi] : 0.0f;
            o[4] = valid ? bs         : 0.0f;
            o[5] = valid ? u.d.cf[bi] : 0.0f;
        }
        bool sup = false;
        if (haveBest && t < TOPK) {
            if (t == bi) {
                sup = true;
            } else {
                float offi = u.d.cf[bi] * 10000.0f;
                float offt = u.d.cf[t]  * 10000.0f;
                float bx1 = u.d.x1[bi] + offi, by1 = u.d.y1[bi] + offi;
                float bx2 = u.d.x2[bi] + offi, by2 = u.d.y2[bi] + offi;
                float tx1 = u.d.x1[t] + offt,  ty1 = u.d.y1[t] + offt;
                float tx2 = u.d.x2[t] + offt,  ty2 = u.d.y2[t] + offt;
                float xx1 = fmaxf(bx1, tx1), yy1 = fmaxf(by1, ty1);
                float xx2 = fminf(bx2, tx2), yy2 = fminf(by2, ty2);
                float inter = fmaxf(xx2 - xx1, 0.0f) * fmaxf(yy2 - yy1, 0.0f);
                float iou = inter / (u.d.ar[bi] + u.d.ar[t] - inter + 1e-9f);
                sup = (iou >= 0.6f);
            }
        }
        unsigned m = __ballot_sync(0xFFFFFFFFu, sup);
        if ((t & 31) == 0 && m) s_alive[t >> 5] &= ~m;
        __syncthreads();
    }
}

// ---------------- launch ----------------
extern "C" void kernel_launch(void* const* d_in, const int* in_sizes, int n_in,
                              void* d_out, int out_size) {
    (void)in_sizes; (void)n_in; (void)out_size;
    const float* lg[5]; const float* bb[5]; const float* ct[5];
    for (int l = 0; l < 5; l++) {
        lg[l] = (const float*)d_in[3 * l + 0];
        bb[l] = (const float*)d_in[3 * l + 1];
        ct[l] = (const float*)d_in[3 * l + 2];
    }
    const float* iminfo = (const float*)d_in[15];
    float* out = (float*)d_out;

    zero_kernel<<<(NB * REP * NBUCK / 4 + 255) / 256, 256>>>();
    dummy_kernel<<<1, 1>>>();
    dummy_kernel<<<1, 1>>>();   // positions score_kernel as launch #4 for ncu capture
    score_kernel<<<dim3(336, NB), 256>>>(lg[0], ct[0], lg[1], ct[1], lg[2], ct[2],
                                         lg[3], ct[3], lg[4], ct[4]);
    pass2_kernel<<<NB, 256>>>();
    pass3_kernel<<<dim3(32, NB), 256>>>();
    sortnms_kernel<<<NB, 1024>>>(bb[0], bb[1], bb[2], bb[3], bb[4], iminfo, out);
}

// round 4
// speedup vs baseline: 2.4417x; 1.0642x over previous
#include <cuda_runtime.h>
#include <math.h>

#define NB 16
#define NC 80
#define NBUCK 16384
#define REP 4
#define SEL_CAP 4096
#define TOPK 1000
#define MAXDET 100

// ---------------- static device scratch (no allocations) ----------------
__device__ int g_hist[NB * REP * NBUCK];
__device__ int g_selCount[NB];
__device__ int g_thr[NB];
__device__ float g_thrX[NB];
__device__ unsigned long long g_sel[NB * SEL_CAP];   // (score_bits<<32)|(~idx)

// ---------------- pass 0: zero scratch ----------------
__global__ void zero_kernel() {
    int i = blockIdx.x * blockDim.x + threadIdx.x;
    int4* p = reinterpret_cast<int4*>(g_hist);
    if (i < NB * REP * NBUCK / 4) p[i] = make_int4(0, 0, 0, 0);
    if (i < NB) g_selCount[i] = 0;
}

// ---------------- pass A: histogram of comb scores ----------------
template<int HW, int LOCOFF>
__device__ __forceinline__ void hist_level(
    const float* __restrict__ lg, const float* __restrict__ ct,
    int b, int chunk, int rep)
{
    constexpr int CHW = NC * HW;
    const float* lp = lg + (size_t)b * CHW;
    const float* cp = ct + (size_t)b * HW;
    int* hist = &g_hist[(b * REP + rep) * NBUCK];
    int base = chunk * 4096;
    #pragma unroll
    for (int k = 0; k < 4; k++) {
        int e = base + (threadIdx.x + k * 256) * 4;
        if (e >= CHW) continue;
        float4 v = *reinterpret_cast<const float4*>(lp + e);
        int c  = e / HW;
        int hw = e - c * HW;
        float xs[4] = {v.x, v.y, v.z, v.w};
        #pragma unroll
        for (int i = 0; i < 4; i++) {
            float x = xs[i];
            if (x > -2.9445f) {               // sigmoid(-2.9445) < 0.05 with margin
                float cls = 1.0f / (1.0f + expf(-x));
                if (cls > 0.05f) {
                    float cen  = 1.0f / (1.0f + expf(-cp[hw + i]));
                    float comb = cls * cen;   // strictly > 0
                    atomicAdd(&hist[__float_as_uint(comb) >> 17], 1);
                }
            }
        }
    }
}

__global__ __launch_bounds__(256) void histA_kernel(
    const float* __restrict__ lg0, const float* __restrict__ ct0,
    const float* __restrict__ lg1, const float* __restrict__ ct1,
    const float* __restrict__ lg2, const float* __restrict__ ct2,
    const float* __restrict__ lg3, const float* __restrict__ ct3,
    const float* __restrict__ lg4, const float* __restrict__ ct4)
{
    int bx = blockIdx.x, b = blockIdx.y, rep = bx & (REP - 1);
    if      (bx < 250) hist_level<12800,     0>(lg0, ct0, b, bx,       rep);
    else if (bx < 313) hist_level< 3200, 12800>(lg1, ct1, b, bx - 250, rep);
    else if (bx < 329) hist_level<  800, 16000>(lg2, ct2, b, bx - 313, rep);
    else if (bx < 334) hist_level<  208, 16800>(lg3, ct3, b, bx - 329, rep);
    else               hist_level<   56, 17008>(lg4, ct4, b, bx - 334, rep);
}

// ---------------- pass 2: per-batch histogram threshold ----------------
__global__ void pass2_kernel() {
    int b = blockIdx.x;
    __shared__ int csum[256];
    __shared__ int sval[64];
    __shared__ int s_j, s_cumbefore;
    int t = threadIdx.x;
    const int* hb = &g_hist[b * REP * NBUCK];

    int s = 0;
    for (int r = t * 64; r < t * 64 + 64; r++) {
        int bucket = NBUCK - 1 - r;
        int v = 0;
        #pragma unroll
        for (int rp = 0; rp < REP; rp++) v += hb[rp * NBUCK + bucket];
        s += v;
    }
    csum[t] = s;
    __syncthreads();
    if (t == 0) {
        int cum = 0, j = 255;
        for (int q = 0; q < 256; q++) {
            if (cum + csum[q] >= TOPK) { j = q; break; }
            cum += csum[q];
        }
        s_j = j; s_cumbefore = cum;
    }
    __syncthreads();
    int j = s_j;
    if (t < 64) {
        int bucket = NBUCK - 1 - (j * 64 + t);
        int v = 0;
        #pragma unroll
        for (int rp = 0; rp < REP; rp++) v += hb[rp * NBUCK + bucket];
        sval[t] = v;
    }
    __syncthreads();
    if (t == 0) {
        int cum = s_cumbefore, thr = 0;
        for (int q = 0; q < 64; q++) {
            cum += sval[q];
            if (cum >= TOPK) { thr = NBUCK - 1 - (j * 64 + q); break; }
        }
        g_thr[b] = thr;                     // 0 => take everything
        float tX = -2.9445f;
        if (thr > 0) {
            float cm = __uint_as_float((unsigned)thr << 17);  // bucket lower edge
            if (cm > 0.0f && cm < 1.0f)
                tX = fmaxf(tX, logf(cm / (1.0f - cm)) - 1e-3f);  // cls >= comb >= cm
        }
        g_thrX[b] = tX;
    }
}

// ---------------- pass B: selective re-read, direct candidate write ----------------
template<int HW, int LOCOFF>
__device__ __forceinline__ void sel_level(
    const float* __restrict__ lg, const float* __restrict__ ct,
    int b, int chunk, unsigned thr, float thrX)
{
    constexpr int CHW = NC * HW;
    const float* lp = lg + (size_t)b * CHW;
    const float* cp = ct + (size_t)b * HW;
    int base = chunk * 4096;
    #pragma unroll
    for (int k = 0; k < 4; k++) {
        int e = base + (threadIdx.x + k * 256) * 4;
        if (e >= CHW) continue;
        float4 v = *reinterpret_cast<const float4*>(lp + e);
        int c  = e / HW;
        int hw = e - c * HW;
        float xs[4] = {v.x, v.y, v.z, v.w};
        #pragma unroll
        for (int i = 0; i < 4; i++) {
            float x = xs[i];
            if (x > thrX) {                         // conservative prefilter
                float cls = 1.0f / (1.0f + expf(-x));
                if (cls > 0.05f) {
                    float cen  = 1.0f / (1.0f + expf(-cp[hw + i]));
                    float comb = cls * cen;
                    unsigned bits = __float_as_uint(comb);
                    if ((bits >> 17) >= thr) {
                        unsigned idx = (unsigned)((LOCOFF + hw + i) * NC + c);
                        int p = atomicAdd(&g_selCount[b], 1);
                        if (p < SEL_CAP)
                            g_sel[b * SEL_CAP + p] =
                                ((unsigned long long)bits << 32) |
                                (unsigned long long)(0xFFFFFFFFu - idx);
                    }
                }
            }
        }
    }
}

__global__ __launch_bounds__(256) void selB_kernel(
    const float* __restrict__ lg0, const float* __restrict__ ct0,
    const float* __restrict__ lg1, const float* __restrict__ ct1,
    const float* __restrict__ lg2, const float* __restrict__ ct2,
    const float* __restrict__ lg3, const float* __restrict__ ct3,
    const float* __restrict__ lg4, const float* __restrict__ ct4)
{
    int bx = blockIdx.x, b = blockIdx.y;
    unsigned thr = (unsigned)g_thr[b];
    float thrX = g_thrX[b];
    if      (bx < 250) sel_level<12800,     0>(lg0, ct0, b, bx,       thr, thrX);
    else if (bx < 313) sel_level< 3200, 12800>(lg1, ct1, b, bx - 250, thr, thrX);
    else if (bx < 329) sel_level<  800, 16000>(lg2, ct2, b, bx - 313, thr, thrX);
    else if (bx < 334) sel_level<  208, 16800>(lg3, ct3, b, bx - 329, thr, thrX);
    else               sel_level<   56, 17008>(lg4, ct4, b, bx - 334, thr, thrX);
}

// ---------------- fused sort + decode + NMS ----------------
__global__ __launch_bounds__(1024) void sortnms_kernel(
    const float* __restrict__ bb0, const float* __restrict__ bb1,
    const float* __restrict__ bb2, const float* __restrict__ bb3,
    const float* __restrict__ bb4, const float* __restrict__ iminfo,
    float* __restrict__ out)
{
    int b = blockIdx.x;
    int t = threadIdx.x;

    __shared__ union {
        unsigned long long key[SEL_CAP];                          // 32 KB
        struct { float ox1[1024], oy1[1024], ox2[1024], oy2[1024],
                       ar[1024], sc[1024]; } d;                   // 24 KB
    } u;
    __shared__ unsigned s_alive[32];
    __shared__ int s_best, s_head;
    __shared__ float s_bestS;

    // pre-zero this batch's output (100 rows x 6)
    if (t < MAXDET * 6) out[(size_t)b * MAXDET * 6 + t] = 0.0f;

    int cnt = min(g_selCount[b], SEL_CAP);
    int n2 = 1024;
    while (n2 < cnt) n2 <<= 1;

    for (int i = t; i < n2; i += blockDim.x)
        u.key[i] = (i < cnt) ? g_sel[b * SEL_CAP + i] : 0ULL;
    __syncthreads();

    // bitonic sort descending: key = (score_bits<<32)|(~idx) -> desc score, asc idx ties
    for (int k = 2; k <= n2; k <<= 1) {
        for (int j = k >> 1; j > 0; j >>= 1) {
            for (int i = t; i < n2; i += blockDim.x) {
                int ixj = i ^ j;
                if (ixj > i) {
                    bool desc = (i & k) == 0;
                    unsigned long long a = u.key[i], c = u.key[ixj];
                    if (desc ? (a < c) : (a > c)) { u.key[i] = c; u.key[ixj] = a; }
                }
            }
            __syncthreads();
        }
    }

    unsigned long long myKey = (t < TOPK) ? u.key[t] : 0ULL;
    __syncthreads();

    // decode: plain coords/class kept in REGISTERS, broadcast data in smem
    float rx1 = 0.f, ry1 = 0.f, rx2 = 0.f, ry2 = 0.f, rsc = 0.f, rcf = 0.f;
    float rox1 = 0.f, roy1 = 0.f, rox2 = 0.f, roy2 = 0.f, rar = 0.f;
    if (t < TOPK) {
        unsigned bits = (unsigned)(myKey >> 32);
        if (bits != 0u) {
            unsigned idx = 0xFFFFFFFFu - (unsigned)(myKey & 0xFFFFFFFFu);
            int loc = (int)(idx / NC);
            int c   = (int)(idx % NC);
            const int offs[5]    = {0, 12800, 16000, 16800, 17008};
            const int Ws[5]      = {128, 64, 32, 16, 8};
            const int HWs[5]     = {12800, 3200, 800, 208, 56};
            const int strides[5] = {8, 16, 32, 64, 128};
            const float* bbs[5]  = {bb0, bb1, bb2, bb3, bb4};
            int lvl = 4;
            if      (loc < 12800) lvl = 0;
            else if (loc < 16000) lvl = 1;
            else if (loc < 16800) lvl = 2;
            else if (loc < 17008) lvl = 3;
            int local = loc - offs[lvl];
            int W = Ws[lvl], HW = HWs[lvl], st = strides[lvl];
            int hh = local / W;
            int ww = local - hh * W;
            float cx = (float)(ww * st + (st >> 1));
            float cy = (float)(hh * st + (st >> 1));
            const float* bp = bbs[lvl] + (size_t)b * 4 * HW + local;
            float r0 = bp[0], r1 = bp[HW], r2 = bp[2 * HW], r3 = bp[3 * HW];
            float ih = iminfo[b * 2 + 0];
            float iw = iminfo[b * 2 + 1];
            rx1 = fminf(fmaxf(cx - r0, 0.0f), iw - 1.0f);
            ry1 = fminf(fmaxf(cy - r1, 0.0f), ih - 1.0f);
            rx2 = fminf(fmaxf(cx + r2, 0.0f), iw - 1.0f);
            ry2 = fminf(fmaxf(cy + r3, 0.0f), ih - 1.0f);
            rsc = sqrtf(__uint_as_float(bits) + 1e-12f);
            rcf = (float)c;
        }
        float off = rcf * 10000.0f;
        rox1 = rx1 + off; roy1 = ry1 + off; rox2 = rx2 + off; roy2 = ry2 + off;
        rar  = fmaxf(rox2 - rox1, 0.0f) * fmaxf(roy2 - roy1, 0.0f);
        u.d.ox1[t] = rox1; u.d.oy1[t] = roy1; u.d.ox2[t] = rox2; u.d.oy2[t] = roy2;
        u.d.ar[t]  = rar;  u.d.sc[t]  = rsc;
    }
    if (t < 32) s_alive[t] = (t < 31) ? 0xFFFFFFFFu : 0x000000FFu;  // 1000 bits
    if (t == 0) s_head = 0;
    __syncthreads();

    // sorted-greedy NMS: first-alive == argmax of remaining (and head is monotone)
    for (int it = 0; it < MAXDET; it++) {
        if (t < 32) {
            int head = s_head;
            unsigned w = (t >= (head >> 5)) ? s_alive[t] : 0u;
            int pos = w ? (t * 32 + __ffs(w) - 1) : 0x7FFFFFFF;
            #pragma unroll
            for (int d = 16; d > 0; d >>= 1)
                pos = min(pos, __shfl_down_sync(0xFFFFFFFFu, pos, d));
            if (t == 0) {
                s_best  = pos;
                s_bestS = (pos < TOPK) ? u.d.sc[pos] : 0.0f;
                s_head  = (pos < TOPK) ? pos : TOPK;
            }
        }
        __syncthreads();
        int bi = s_best;
        float bs = s_bestS;
        if (bs <= 0.0f) break;               // rest of output stays zero (matches ref)
        if (t == bi) {                       // winner writes its own row
            float* o = out + (size_t)(b * MAXDET + it) * 6;
            o[0] = rx1; o[1] = ry1; o[2] = rx2; o[3] = ry2; o[4] = rsc; o[5] = rcf;
        }
        bool sup = false;
        if (t < TOPK) {
            float bx1 = u.d.ox1[bi], by1 = u.d.oy1[bi];
            float bx2 = u.d.ox2[bi], by2 = u.d.oy2[bi];
            float bar = u.d.ar[bi];
            float xx1 = fmaxf(bx1, rox1), yy1 = fmaxf(by1, roy1);
            float xx2 = fminf(bx2, rox2), yy2 = fminf(by2, roy2);
            float inter = fmaxf(xx2 - xx1, 0.0f) * fmaxf(yy2 - yy1, 0.0f);
            float iou = inter / (bar + rar - inter + 1e-9f);
            sup = (iou >= 0.6f) || (t == bi);
        }
        unsigned m = __ballot_sync(0xFFFFFFFFu, sup);
        if ((t & 31) == 0 && m) s_alive[t >> 5] &= ~m;
        __syncthreads();
    }
}

// ---------------- launch ----------------
extern "C" void kernel_launch(void* const* d_in, const int* in_sizes, int n_in,
                              void* d_out, int out_size) {
    (void)in_sizes; (void)n_in; (void)out_size;
    const float* lg[5]; const float* bb[5]; const float* ct[5];
    for (int l = 0; l < 5; l++) {
        lg[l] = (const float*)d_in[3 * l + 0];
        bb[l] = (const float*)d_in[3 * l + 1];
        ct[l] = (const float*)d_in[3 * l + 2];
    }
    const float* iminfo = (const float*)d_in[15];
    float* out = (float*)d_out;

    zero_kernel<<<(NB * REP * NBUCK / 4 + 255) / 256, 256>>>();
    histA_kernel<<<dim3(336, NB), 256>>>(lg[0], ct[0], lg[1], ct[1], lg[2], ct[2],
                                         lg[3], ct[3], lg[4], ct[4]);
    pass2_kernel<<<NB, 256>>>();
    selB_kernel<<<dim3(336, NB), 256>>>(lg[0], ct[0], lg[1], ct[1], lg[2], ct[2],
                                        lg[3], ct[3], lg[4], ct[4]);  // ncu launch #4
    sortnms_kernel<<<NB, 1024>>>(bb[0], bb[1], bb[2], bb[3], bb[4], iminfo, out);
}